// round 8
// baseline (speedup 1.0000x reference)
#include <cuda_runtime.h>
#include <cuda_fp16.h>

#define MULD 32
#define NPB 16          // nodes per block (8 warps x 2 nodes)
#define THREADS 256

// Packed fp16 weight streams (filled by pack_kernel on every launch).
//   g_Wab_h[(i*32+j)*32+k] = { h2(w0x,w0y), h2(w1y,w1x) }
//   g_Wc_h [(i*32+j)*32+k] =   h2(w2x,w2y)
__device__ uint2    g_Wab_h[32768];
__device__ unsigned g_Wc_h[32768];

typedef unsigned long long u64;

__device__ __forceinline__ u64 pk(float lo, float hi) {
    u64 r; asm("mov.b64 %0, {%1, %2};" : "=l"(r) : "f"(lo), "f"(hi)); return r;
}
__device__ __forceinline__ void fma2(u64& d, u64 a, u64 b) {
    asm("fma.rn.f32x2 %0, %1, %2, %0;" : "+l"(d) : "l"(a), "l"(b));
}
__device__ __forceinline__ float2 up(u64 v) {
    float2 r; asm("mov.b64 {%0, %1}, %2;" : "=f"(r.x), "=f"(r.y) : "l"(v)); return r;
}
__device__ __forceinline__ unsigned s2u(const void* p) {
    return (unsigned)__cvta_generic_to_shared(p);
}
__device__ __forceinline__ void cp8(unsigned dst, const void* src) {
    asm volatile("cp.async.ca.shared.global [%0], [%1], 8;" :: "r"(dst), "l"(src));
}
__device__ __forceinline__ void cp4(unsigned dst, const void* src) {
    asm volatile("cp.async.ca.shared.global [%0], [%1], 4;" :: "r"(dst), "l"(src));
}
__device__ __forceinline__ void cp_commit() {
    asm volatile("cp.async.commit_group;" ::: "memory");
}
__device__ __forceinline__ void cp_wait1() {
    asm volatile("cp.async.wait_group 1;" ::: "memory");
}

__global__ void pack_kernel(const float* __restrict__ W3_0e,
                            const float* __restrict__ W3_1o,
                            const float* __restrict__ W3_1e,
                            const float* __restrict__ W3_2e)
{
    int t = blockIdx.x * blockDim.x + threadIdx.x;
    if (t < 32768) {
        __half2 h01 = __floats2half2_rn(W3_0e[t], W3_0e[32768 + t]);   // (w0x,w0y)
        __half2 h23 = __floats2half2_rn(W3_1o[32768 + t], W3_1o[t]);   // (w1y,w1x)
        __half2 hc  = __floats2half2_rn(W3_1e[t], W3_2e[t]);           // (w2x,w2y)
        uint2 w; w.x = *(unsigned*)&h01; w.y = *(unsigned*)&h23;
        g_Wab_h[t] = w;
        g_Wc_h[t]  = *(unsigned*)&hc;
    }
}

// SMEM (dynamic, 40KB), double-buffered fp16 weights:
//   wABh: uint2[2][1024]   16KB  @0
//   wCh : uint [2][1024]    8KB  @16KB
//   Ash : float4[16][32]    8KB  @24KB
//   Bsh : float4[16][32]    8KB  @32KB   (s, v0, v1, v2)
//   xs (prologue) overlays wABh: float[16][128] 8KB

__global__ __launch_bounds__(THREADS, 3)
void td_kernel(const float* __restrict__ x,
               const float* __restrict__ W1_0, const float* __restrict__ W1_1,
               const float* __restrict__ W2_0, const float* __restrict__ W2_1,
               float* __restrict__ out, int N)
{
    extern __shared__ float smem[];
    uint2*    wABh = (uint2*)smem;              // [2][1024]
    unsigned* wCh  = (unsigned*)(wABh + 2048);  // [2][1024]
    float4*   Ash  = (float4*)(wCh + 2048);     // [512]
    float4*   Bsh  = Ash + NPB * 32;            // [512]
    float*    xs   = smem;                      // prologue overlay

    const int tid = threadIdx.x;
    const int n0  = blockIdx.x * NPB;

    // ---- stage x rows ----
    for (int e = tid; e < NPB * 128; e += THREADS) {
        int node = e >> 7;
        xs[e] = (n0 + node < N) ? x[(size_t)(n0 + node) * 128 + (e & 127)] : 0.0f;
    }
    __syncthreads();

    // ---- prologue: A=(s@W1_0, v@W1_1), B=(s@W2_0, v@W2_1) ----
    for (int t = tid; t < NPB * 32 * 2; t += THREADS) {
        int which = (t >= NPB * 32);
        int tt = t & (NPB * 32 - 1);
        int node = tt >> 5, i = tt & 31;
        const float* Ws = which ? W2_0 : W1_0;
        const float* Wv = which ? W2_1 : W1_1;
        const float* xr = xs + node * 128;
        float s = 0.f, v0 = 0.f, v1 = 0.f, v2 = 0.f;
        #pragma unroll
        for (int m = 0; m < 32; ++m) {
            float ws = Ws[m * 32 + i];
            float wv = Wv[m * 32 + i];
            s  += xr[m] * ws;
            v0 += xr[32 + 3 * m + 0] * wv;
            v1 += xr[32 + 3 * m + 1] * wv;
            v2 += xr[32 + 3 * m + 2] * wv;
        }
        float4 r = make_float4(s, v0, v1, v2);
        if (which) Bsh[node * 32 + i] = r;
        else       Ash[node * 32 + i] = r;
    }
    __syncthreads();   // xs overlay fully consumed

    // ---- async-stage chunks 0 and 1 ----
    const unsigned sAB = s2u(wABh);
    const unsigned sC  = s2u(wCh);
    {
        #pragma unroll
        for (int r = 0; r < 4; ++r) {
            int e = tid + r * THREADS;
            cp8(sAB + e * 8, g_Wab_h + e);
            cp4(sC  + e * 4, g_Wc_h  + e);
        }
        cp_commit();
        #pragma unroll
        for (int r = 0; r < 4; ++r) {
            int e = tid + r * THREADS;
            cp8(sAB + 8192 + e * 8, g_Wab_h + 1024 + e);
            cp4(sC  + 4096 + e * 4, g_Wc_h  + 1024 + e);
        }
        cp_commit();
    }

    const int wid = tid >> 5;
    const int k   = tid & 31;
    const int nA  = wid * 2;
    const int nB  = wid * 2 + 1;

    float acc[2][13];
    #pragma unroll
    for (int a = 0; a < 2; ++a)
        #pragma unroll
        for (int q = 0; q < 13; ++q) acc[a][q] = 0.f;

    for (int i = 0; i < 32; ++i) {
        // Pending groups: {G_i, G_{i+1}} (tail: {G31, E30}); wait_group 1
        // retires all but the newest => chunk i complete.
        cp_wait1();
        __syncthreads();

        const uint2*    wAB = wABh + (i & 1) * 1024;
        const unsigned* wC  = wCh  + (i & 1) * 1024;

        u64 MA0=0, MA1=0, MA2=0, MA3=0, MA4=0, MA5=0, MA6=0;
        u64 MB0=0, MB1=0, MB2=0, MB3=0, MB4=0, MB5=0, MB6=0;

        const float4* BA = Bsh + nA * 32;
        const float4* BB = Bsh + nB * 32;

        #pragma unroll 8
        for (int j = 0; j < 32; ++j) {
            const int idx = j * 32 + k;
            uint2 wab = wAB[idx];            // h2(w0x,w0y), h2(w1y,w1x)
            unsigned wcc = wC[idx];          // h2(w2x,w2y)
            float2 w01 = __half22float2(*(const __half2*)&wab.x);
            float2 w23 = __half22float2(*(const __half2*)&wab.y);
            float2 wc2 = __half22float2(*(const __half2*)&wcc);
            u64 P1  = pk(w01.x, w01.y);   // (w0x, w0y)
            u64 P2  = pk(w01.y, w01.y);   // (w0y, w0y)
            u64 P3  = pk(w23.x, w23.y);   // (w1y, w1x)
            u64 P4  = pk(w23.y, w23.y);   // (w1x, w1x)
            u64 S2x = pk(wc2.x, wc2.x);   // (w2x, w2x)
            u64 S2y = pk(wc2.y, wc2.y);   // (w2y, w2y)
            u64 CF  = pk(wc2.x, wc2.y);   // (w2x, w2y)

            ulonglong2 ba = *(const ulonglong2*)&BA[j];     // (s,v0),(v1,v2)
            float2 baxy = up(ba.x);
            u64 Dav0 = pk(baxy.y, baxy.y);                  // (v0, v0)
            fma2(MA0, P1,  ba.x);   // (m0,  m1)
            fma2(MA1, P2,  ba.y);   // (m2,  m3)
            fma2(MA2, P3,  ba.x);   // (m7,  m4)
            fma2(MA3, P4,  ba.y);   // (m5,  m6)
            fma2(MA4, S2x, ba.y);   // (m9,  m10)
            fma2(MA5, S2y, ba.y);   // (m12, m13)
            fma2(MA6, CF,  Dav0);   // (m8,  m11)

            ulonglong2 bb = *(const ulonglong2*)&BB[j];
            float2 bbxy = up(bb.x);
            u64 Dbv0 = pk(bbxy.y, bbxy.y);
            fma2(MB0, P1,  bb.x);
            fma2(MB1, P2,  bb.y);
            fma2(MB2, P3,  bb.x);
            fma2(MB3, P4,  bb.y);
            fma2(MB4, S2x, bb.y);
            fma2(MB5, S2y, bb.y);
            fma2(MB6, CF,  Dbv0);
        }

        // ---- fold with A_i ----
        {
            float4 a0 = Ash[nA * 32 + i];
            float2 u0 = up(MA0), u1 = up(MA1), u2 = up(MA2),
                   u3 = up(MA3), u4 = up(MA4), u5 = up(MA5), u6 = up(MA6);
            float m0 = u0.x, m1 = u0.y, m2 = u1.x, m3 = u1.y;
            float m7 = u2.x, m4 = u2.y, m5 = u3.x, m6 = u3.y;
            float m9 = u4.x, m10 = u4.y, m12 = u5.x, m13 = u5.y;
            float m8 = u6.x, m11 = u6.y;
            acc[0][0]  += a0.x * m0;
            acc[0][1]  += a0.y * m1  + a0.z * m2  + a0.w * m3;
            acc[0][2]  += a0.x * m4  + a0.y * m7;
            acc[0][3]  += a0.x * m5  + a0.z * m7;
            acc[0][4]  += a0.x * m6  + a0.w * m7;
            acc[0][5]  += a0.z * m10 - a0.w * m9;
            acc[0][6]  += a0.w * m8  - a0.y * m10;
            acc[0][7]  += a0.y * m9  - a0.z * m8;
            acc[0][8]  += a0.y * m13 + a0.w * m11;
            acc[0][9]  += a0.y * m12 + a0.z * m11;
            acc[0][10] += 2.f * a0.z * m12 - a0.y * m11 - a0.w * m13;
            acc[0][11] += a0.z * m13 + a0.w * m12;
            acc[0][12] += a0.w * m13 - a0.y * m11;
        }
        {
            float4 a1 = Ash[nB * 32 + i];
            float2 u0 = up(MB0), u1 = up(MB1), u2 = up(MB2),
                   u3 = up(MB3), u4 = up(MB4), u5 = up(MB5), u6 = up(MB6);
            float m0 = u0.x, m1 = u0.y, m2 = u1.x, m3 = u1.y;
            float m7 = u2.x, m4 = u2.y, m5 = u3.x, m6 = u3.y;
            float m9 = u4.x, m10 = u4.y, m12 = u5.x, m13 = u5.y;
            float m8 = u6.x, m11 = u6.y;
            acc[1][0]  += a1.x * m0;
            acc[1][1]  += a1.y * m1  + a1.z * m2  + a1.w * m3;
            acc[1][2]  += a1.x * m4  + a1.y * m7;
            acc[1][3]  += a1.x * m5  + a1.z * m7;
            acc[1][4]  += a1.x * m6  + a1.w * m7;
            acc[1][5]  += a1.z * m10 - a1.w * m9;
            acc[1][6]  += a1.w * m8  - a1.y * m10;
            acc[1][7]  += a1.y * m9  - a1.z * m8;
            acc[1][8]  += a1.y * m13 + a1.w * m11;
            acc[1][9]  += a1.y * m12 + a1.z * m11;
            acc[1][10] += 2.f * a1.z * m12 - a1.y * m11 - a1.w * m13;
            acc[1][11] += a1.z * m13 + a1.w * m12;
            acc[1][12] += a1.w * m13 - a1.y * m11;
        }

        __syncthreads();   // all warps done with buffer (i&1)

        // ---- async-stage chunk i+2 into buffer (i&1) ----
        if (i + 2 < 32) {
            unsigned bAB = sAB + (i & 1) * 8192;
            unsigned bC  = sC  + (i & 1) * 4096;
            int goff = (i + 2) * 1024;
            #pragma unroll
            for (int r = 0; r < 4; ++r) {
                int e = tid + r * THREADS;
                cp8(bAB + e * 8, g_Wab_h + goff + e);
                cp4(bC  + e * 4, g_Wc_h  + goff + e);
            }
        }
        cp_commit();   // fixed group count per iteration
    }

    // ---- outputs ----
    const float C0  = -0.57735026918962576f;
    const float C1  = -0.70710678118654752f;
    const float C2  =  0.70710678118654752f;
    const float C2z =  0.40824829046386302f;

    #pragma unroll
    for (int a = 0; a < 2; ++a) {
        int node = n0 + nA + a;
        if (node >= N) continue;
        float* o = out + (size_t)node * 384;
        const float* c = acc[a];
        o[k] = c[0] + C0 * c[1];
        o[32  + 3 * k + 0] = c[2];
        o[32  + 3 * k + 1] = c[3];
        o[32  + 3 * k + 2] = c[4];
        o[128 + 3 * k + 0] = C1 * c[5];
        o[128 + 3 * k + 1] = C1 * c[6];
        o[128 + 3 * k + 2] = C1 * c[7];
        o[224 + 5 * k + 0] = C2 * c[8];
        o[224 + 5 * k + 1] = C2 * c[9];
        o[224 + 5 * k + 2] = C2z * c[10];
        o[224 + 5 * k + 3] = C2 * c[11];
        o[224 + 5 * k + 4] = C2 * c[12];
    }
}

extern "C" void kernel_launch(void* const* d_in, const int* in_sizes, int n_in,
                              void* d_out, int out_size)
{
    const float* x     = (const float*)d_in[0];
    const float* W1_0  = (const float*)d_in[1];
    const float* W1_1  = (const float*)d_in[2];
    const float* W2_0  = (const float*)d_in[3];
    const float* W2_1  = (const float*)d_in[4];
    const float* W3_0e = (const float*)d_in[5];
    const float* W3_1o = (const float*)d_in[6];
    const float* W3_1e = (const float*)d_in[7];
    const float* W3_2e = (const float*)d_in[8];

    int N = in_sizes[0] / (4 * MULD);
    int blocks = (N + NPB - 1) / NPB;
    size_t smem = 2048 * sizeof(uint2)             // wABh 16KB
                + 2048 * sizeof(unsigned)          // wCh   8KB
                + 2 * NPB * 32 * sizeof(float4);   // Ash+Bsh 16KB => 40KB

    cudaFuncSetAttribute(td_kernel, cudaFuncAttributeMaxDynamicSharedMemorySize,
                         (int)smem);

    pack_kernel<<<128, 256>>>(W3_0e, W3_1o, W3_1e, W3_2e);
    td_kernel<<<blocks, THREADS, smem>>>(x, W1_0, W1_1, W2_0, W2_1,
                                         (float*)d_out, N);
}

// round 9
// speedup vs baseline: 1.0704x; 1.0704x over previous
#include <cuda_runtime.h>

#define MULD 32
#define NPB 16          // nodes per block (8 warps x 2 nodes)
#define THREADS 256

// Packed weight streams (filled by pack_kernel on every launch).
//   g_Wab[(i*32+j)*32+k] = (w0x, w0y, w1y, w1x)
//   g_Wc [(i*32+j)*32+k] = (w2x, w2y)
__device__ float4 g_Wab[32768];
__device__ float2 g_Wc[32768];

typedef unsigned long long u64;

__device__ __forceinline__ u64 pk(float lo, float hi) {
    u64 r; asm("mov.b64 %0, {%1, %2};" : "=l"(r) : "f"(lo), "f"(hi)); return r;
}
__device__ __forceinline__ void fma2(u64& d, u64 a, u64 b) {
    asm("fma.rn.f32x2 %0, %1, %2, %0;" : "+l"(d) : "l"(a), "l"(b));
}
__device__ __forceinline__ float2 up(u64 v) {
    float2 r; asm("mov.b64 {%0, %1}, %2;" : "=f"(r.x), "=f"(r.y) : "l"(v)); return r;
}
__device__ __forceinline__ unsigned s2u(const void* p) {
    return (unsigned)__cvta_generic_to_shared(p);
}
__device__ __forceinline__ void cp16(unsigned dst, const void* src) {
    asm volatile("cp.async.cg.shared.global [%0], [%1], 16;" :: "r"(dst), "l"(src));
}
__device__ __forceinline__ void cp8(unsigned dst, const void* src) {
    asm volatile("cp.async.ca.shared.global [%0], [%1], 8;" :: "r"(dst), "l"(src));
}
__device__ __forceinline__ void cp_commit() {
    asm volatile("cp.async.commit_group;" ::: "memory");
}
__device__ __forceinline__ void cp_wait0() {
    asm volatile("cp.async.wait_group 0;" ::: "memory");
}

__global__ void pack_kernel(const float* __restrict__ W3_0e,
                            const float* __restrict__ W3_1o,
                            const float* __restrict__ W3_1e,
                            const float* __restrict__ W3_2e)
{
    int t = blockIdx.x * blockDim.x + threadIdx.x;
    if (t < 32768) {
        g_Wab[t] = make_float4(W3_0e[t], W3_0e[32768 + t],
                               W3_1o[32768 + t], W3_1o[t]);
        g_Wc[t]  = make_float2(W3_1e[t], W3_2e[t]);
    }
}

// SMEM (dynamic, 64KB), double-buffered fp32 weights:
//   wABbuf: float4[2][1024]  32KB  @0
//   wCbuf : float2[2][1024]  16KB  @32KB
//   Ash: float4[16][32]       8KB  @48KB
//   Bsh: float4[16][32]       8KB  @56KB   (s, v0, v1, v2)
//   xs (prologue) overlays wABbuf: float[16][128] 8KB

__global__ __launch_bounds__(THREADS, 3)
void td_kernel(const float* __restrict__ x,
               const float* __restrict__ W1_0, const float* __restrict__ W1_1,
               const float* __restrict__ W2_0, const float* __restrict__ W2_1,
               float* __restrict__ out, int N)
{
    extern __shared__ float smem[];
    float4* wABbuf = (float4*)smem;             // [2][1024]
    float2* wCbuf  = (float2*)(wABbuf + 2048);  // [2][1024]
    float4* Ash    = (float4*)(wCbuf + 2048);   // [512]
    float4* Bsh    = Ash + NPB * 32;            // [512]
    float*  xs     = smem;                      // prologue overlay

    const int tid = threadIdx.x;
    const int n0  = blockIdx.x * NPB;

    // ---- stage x rows ----
    for (int e = tid; e < NPB * 128; e += THREADS) {
        int node = e >> 7;
        xs[e] = (n0 + node < N) ? x[(size_t)(n0 + node) * 128 + (e & 127)] : 0.0f;
    }
    __syncthreads();

    // ---- prologue: A=(s@W1_0, v@W1_1), B=(s@W2_0, v@W2_1) ----
    for (int t = tid; t < NPB * 32 * 2; t += THREADS) {
        int which = (t >= NPB * 32);
        int tt = t & (NPB * 32 - 1);
        int node = tt >> 5, i = tt & 31;
        const float* Ws = which ? W2_0 : W1_0;
        const float* Wv = which ? W2_1 : W1_1;
        const float* xr = xs + node * 128;
        float s = 0.f, v0 = 0.f, v1 = 0.f, v2 = 0.f;
        #pragma unroll
        for (int m = 0; m < 32; ++m) {
            float ws = Ws[m * 32 + i];
            float wv = Wv[m * 32 + i];
            s  += xr[m] * ws;
            v0 += xr[32 + 3 * m + 0] * wv;
            v1 += xr[32 + 3 * m + 1] * wv;
            v2 += xr[32 + 3 * m + 2] * wv;
        }
        float4 r = make_float4(s, v0, v1, v2);
        if (which) Bsh[node * 32 + i] = r;
        else       Ash[node * 32 + i] = r;
    }
    __syncthreads();   // xs overlay fully consumed

    const unsigned sAB = s2u(wABbuf);
    const unsigned sC  = s2u(wCbuf);

    // ---- async-stage chunk 0 into buffer 0 ----
    {
        #pragma unroll
        for (int r = 0; r < 4; ++r) {
            int e = tid + r * THREADS;
            cp16(sAB + e * 16, g_Wab + e);
            cp8 (sC  + e * 8,  g_Wc  + e);
        }
        cp_commit();
    }

    const int wid = tid >> 5;
    const int k   = tid & 31;
    const int nA  = wid * 2;
    const int nB  = wid * 2 + 1;

    float acc[2][13];
    #pragma unroll
    for (int a = 0; a < 2; ++a)
        #pragma unroll
        for (int q = 0; q < 13; ++q) acc[a][q] = 0.f;

    for (int i = 0; i < 32; ++i) {
        // Only chunk i is pending (issued one full compute-phase ago).
        cp_wait0();
        __syncthreads();   // chunk i visible to all; prior reads of the other
                           // buffer (iter i-1) are also fenced by this barrier.

        // ---- issue chunk i+1 into the other buffer; lands during compute ----
        if (i + 1 < 32) {
            unsigned bAB = sAB + ((i + 1) & 1) * 16384;
            unsigned bC  = sC  + ((i + 1) & 1) * 8192;
            int goff = (i + 1) * 1024;
            #pragma unroll
            for (int r = 0; r < 4; ++r) {
                int e = tid + r * THREADS;
                cp16(bAB + e * 16, g_Wab + goff + e);
                cp8 (bC  + e * 8,  g_Wc  + goff + e);
            }
            cp_commit();
        }

        const float4* wAB = wABbuf + (i & 1) * 1024;
        const u64*    wCu = (const u64*)(wCbuf + (i & 1) * 1024);

        u64 MA0=0, MA1=0, MA2=0, MA3=0, MA4=0, MA5=0, MA6=0;
        u64 MB0=0, MB1=0, MB2=0, MB3=0, MB4=0, MB5=0, MB6=0;

        const ulonglong2* wABp = (const ulonglong2*)(wAB + k);
        const u64*        wCp  = wCu + k;
        const float4* BA = Bsh + nA * 32;
        const float4* BB = Bsh + nB * 32;

        #pragma unroll 8
        for (int j = 0; j < 32; ++j) {
            ulonglong2 w01 = wABp[j * 32];      // (w0x,w0y),(w1y,w1x)
            u64 cfu = wCp[j * 32];              // (w2x, w2y)
            float2 p1f = up(w01.x);
            float2 p3f = up(w01.y);
            float2 rf  = up(cfu);
            u64 P2  = pk(p1f.y, p1f.y);   // (w0y, w0y)
            u64 P4  = pk(p3f.y, p3f.y);   // (w1x, w1x)
            u64 S2x = pk(rf.x, rf.x);     // (w2x, w2x)
            u64 S2y = pk(rf.y, rf.y);     // (w2y, w2y)

            ulonglong2 ba = *(const ulonglong2*)&BA[j];     // (s,v0),(v1,v2)
            float2 baxy = up(ba.x);
            u64 Dav0 = pk(baxy.y, baxy.y);                  // (v0, v0)
            fma2(MA0, w01.x, ba.x);   // (m0,  m1)
            fma2(MA1, P2,    ba.y);   // (m2,  m3)
            fma2(MA2, w01.y, ba.x);   // (m7,  m4)
            fma2(MA3, P4,    ba.y);   // (m5,  m6)
            fma2(MA4, S2x,   ba.y);   // (m9,  m10)
            fma2(MA5, S2y,   ba.y);   // (m12, m13)
            fma2(MA6, cfu,   Dav0);   // (m8,  m11)

            ulonglong2 bb = *(const ulonglong2*)&BB[j];
            float2 bbxy = up(bb.x);
            u64 Dbv0 = pk(bbxy.y, bbxy.y);
            fma2(MB0, w01.x, bb.x);
            fma2(MB1, P2,    bb.y);
            fma2(MB2, w01.y, bb.x);
            fma2(MB3, P4,    bb.y);
            fma2(MB4, S2x,   bb.y);
            fma2(MB5, S2y,   bb.y);
            fma2(MB6, cfu,   Dbv0);
        }

        // ---- fold with A_i ----
        {
            float4 a0 = Ash[nA * 32 + i];
            float2 u0 = up(MA0), u1 = up(MA1), u2 = up(MA2),
                   u3 = up(MA3), u4 = up(MA4), u5 = up(MA5), u6 = up(MA6);
            float m0 = u0.x, m1 = u0.y, m2 = u1.x, m3 = u1.y;
            float m7 = u2.x, m4 = u2.y, m5 = u3.x, m6 = u3.y;
            float m9 = u4.x, m10 = u4.y, m12 = u5.x, m13 = u5.y;
            float m8 = u6.x, m11 = u6.y;
            acc[0][0]  += a0.x * m0;
            acc[0][1]  += a0.y * m1  + a0.z * m2  + a0.w * m3;
            acc[0][2]  += a0.x * m4  + a0.y * m7;
            acc[0][3]  += a0.x * m5  + a0.z * m7;
            acc[0][4]  += a0.x * m6  + a0.w * m7;
            acc[0][5]  += a0.z * m10 - a0.w * m9;
            acc[0][6]  += a0.w * m8  - a0.y * m10;
            acc[0][7]  += a0.y * m9  - a0.z * m8;
            acc[0][8]  += a0.y * m13 + a0.w * m11;
            acc[0][9]  += a0.y * m12 + a0.z * m11;
            acc[0][10] += 2.f * a0.z * m12 - a0.y * m11 - a0.w * m13;
            acc[0][11] += a0.z * m13 + a0.w * m12;
            acc[0][12] += a0.w * m13 - a0.y * m11;
        }
        {
            float4 a1 = Ash[nB * 32 + i];
            float2 u0 = up(MB0), u1 = up(MB1), u2 = up(MB2),
                   u3 = up(MB3), u4 = up(MB4), u5 = up(MB5), u6 = up(MB6);
            float m0 = u0.x, m1 = u0.y, m2 = u1.x, m3 = u1.y;
            float m7 = u2.x, m4 = u2.y, m5 = u3.x, m6 = u3.y;
            float m9 = u4.x, m10 = u4.y, m12 = u5.x, m13 = u5.y;
            float m8 = u6.x, m11 = u6.y;
            acc[1][0]  += a1.x * m0;
            acc[1][1]  += a1.y * m1  + a1.z * m2  + a1.w * m3;
            acc[1][2]  += a1.x * m4  + a1.y * m7;
            acc[1][3]  += a1.x * m5  + a1.z * m7;
            acc[1][4]  += a1.x * m6  + a1.w * m7;
            acc[1][5]  += a1.z * m10 - a1.w * m9;
            acc[1][6]  += a1.w * m8  - a1.y * m10;
            acc[1][7]  += a1.y * m9  - a1.z * m8;
            acc[1][8]  += a1.y * m13 + a1.w * m11;
            acc[1][9]  += a1.y * m12 + a1.z * m11;
            acc[1][10] += 2.f * a1.z * m12 - a1.y * m11 - a1.w * m13;
            acc[1][11] += a1.z * m13 + a1.w * m12;
            acc[1][12] += a1.w * m13 - a1.y * m11;
        }
    }

    // ---- outputs ----
    const float C0  = -0.57735026918962576f;
    const float C1  = -0.70710678118654752f;
    const float C2  =  0.70710678118654752f;
    const float C2z =  0.40824829046386302f;

    #pragma unroll
    for (int a = 0; a < 2; ++a) {
        int node = n0 + nA + a;
        if (node >= N) continue;
        float* o = out + (size_t)node * 384;
        const float* c = acc[a];
        o[k] = c[0] + C0 * c[1];
        o[32  + 3 * k + 0] = c[2];
        o[32  + 3 * k + 1] = c[3];
        o[32  + 3 * k + 2] = c[4];
        o[128 + 3 * k + 0] = C1 * c[5];
        o[128 + 3 * k + 1] = C1 * c[6];
        o[128 + 3 * k + 2] = C1 * c[7];
        o[224 + 5 * k + 0] = C2 * c[8];
        o[224 + 5 * k + 1] = C2 * c[9];
        o[224 + 5 * k + 2] = C2z * c[10];
        o[224 + 5 * k + 3] = C2 * c[11];
        o[224 + 5 * k + 4] = C2 * c[12];
    }
}

extern "C" void kernel_launch(void* const* d_in, const int* in_sizes, int n_in,
                              void* d_out, int out_size)
{
    const float* x     = (const float*)d_in[0];
    const float* W1_0  = (const float*)d_in[1];
    const float* W1_1  = (const float*)d_in[2];
    const float* W2_0  = (const float*)d_in[3];
    const float* W2_1  = (const float*)d_in[4];
    const float* W3_0e = (const float*)d_in[5];
    const float* W3_1o = (const float*)d_in[6];
    const float* W3_1e = (const float*)d_in[7];
    const float* W3_2e = (const float*)d_in[8];

    int N = in_sizes[0] / (4 * MULD);
    int blocks = (N + NPB - 1) / NPB;
    size_t smem = 2048 * sizeof(float4)            // wABbuf 32KB
                + 2048 * sizeof(float2)            // wCbuf  16KB
                + 2 * NPB * 32 * sizeof(float4);   // Ash+Bsh 16KB => 64KB

    cudaFuncSetAttribute(td_kernel, cudaFuncAttributeMaxDynamicSharedMemorySize,
                         (int)smem);

    pack_kernel<<<128, 256>>>(W3_0e, W3_1o, W3_1e, W3_2e);
    td_kernel<<<blocks, THREADS, smem>>>(x, W1_0, W1_1, W2_0, W2_1,
                                         (float*)d_out, N);
}

// round 10
// speedup vs baseline: 3.0839x; 2.8810x over previous
#include <cuda_runtime.h>

#define NPB 16
#define THREADS 256

// Fragment-major tf32 weights, packed by pack_w every launch.
// g_Wt[(((i*6 + q)*4 + kc)*4 + kt)*32 + lane] = float2(bits):
//   .x = tf32( Wq[i*32 + kc*8 + (lane&3)    ][kt*8 + (lane>>2)] )
//   .y = tf32( Wq[i*32 + kc*8 + (lane&3) + 4][kt*8 + (lane>>2)] )
// streams q: 0=w0x(W3_0e lo) 1=w0y(W3_0e hi) 2=w1y(W3_1o hi) 3=w1x(W3_1o lo)
//            4=w2x(W3_1e)    5=w2y(W3_2e)
__device__ __align__(16) float2 g_Wt[98304];

__device__ __forceinline__ unsigned f2tf(float f) {
    unsigned u; asm("cvt.rna.tf32.f32 %0, %1;" : "=r"(u) : "f"(f)); return u;
}
__device__ __forceinline__ void mma8(float& d0, float& d1, float& d2, float& d3,
                                     unsigned a0, unsigned a1, unsigned a2, unsigned a3,
                                     unsigned b0, unsigned b1) {
    asm volatile("mma.sync.aligned.m16n8k8.row.col.f32.tf32.tf32.f32 "
                 "{%0,%1,%2,%3}, {%4,%5,%6,%7}, {%8,%9}, {%0,%1,%2,%3};"
                 : "+f"(d0), "+f"(d1), "+f"(d2), "+f"(d3)
                 : "r"(a0), "r"(a1), "r"(a2), "r"(a3), "r"(b0), "r"(b1));
}
__device__ __forceinline__ unsigned s2u(const void* p) {
    return (unsigned)__cvta_generic_to_shared(p);
}
__device__ __forceinline__ void cp16(unsigned dst, const void* src) {
    asm volatile("cp.async.cg.shared.global [%0], [%1], 16;" :: "r"(dst), "l"(src));
}
__device__ __forceinline__ void cp_commit() {
    asm volatile("cp.async.commit_group;" ::: "memory");
}
__device__ __forceinline__ void cp_wait0() {
    asm volatile("cp.async.wait_group 0;" ::: "memory");
}
__device__ __forceinline__ void barall() {
    asm volatile("bar.sync 0, %0;" :: "n"(THREADS) : "memory");
}

__global__ void pack_w(const float* __restrict__ W3_0e, const float* __restrict__ W3_1o,
                       const float* __restrict__ W3_1e, const float* __restrict__ W3_2e)
{
    int t = blockIdx.x * blockDim.x + threadIdx.x;
    if (t >= 98304) return;
    int l = t & 31, r = t >> 5;
    int kt = r & 3;  r >>= 2;
    int kc = r & 3;  r >>= 2;
    int q  = r % 6;
    int i  = r / 6;
    int j0 = kc * 8 + (l & 3);
    int k  = kt * 8 + (l >> 2);
    int g0 = (i * 32 + j0) * 32 + k;
    int g1 = (i * 32 + j0 + 4) * 32 + k;
    const float* src; int off = 0;
    switch (q) {
        case 0: src = W3_0e; off = 0;     break;
        case 1: src = W3_0e; off = 32768; break;
        case 2: src = W3_1o; off = 32768; break;
        case 3: src = W3_1o; off = 0;     break;
        case 4: src = W3_1e; off = 0;     break;
        default: src = W3_2e; off = 0;    break;
    }
    unsigned u0 = f2tf(src[off + g0]);
    unsigned u1 = f2tf(src[off + g1]);
    g_Wt[t] = make_float2(__uint_as_float(u0), __uint_as_float(u1));
}

// SMEM (dynamic, 64KB):
//   wbuf: float2[2][3072]  48KB  @0      (per-i weight fragments, double buffer)
//   Ash : float4[16][32]    8KB  @48KB   (s1,v1x,v1y,v1z)
//   Bsh : float4[16][32]    8KB  @56KB   (s2,v2x,v2y,v2z)
//   xs (prologue) overlays wbuf: float[16][128] 8KB

#define LDB(B, Q) { \
    _Pragma("unroll") \
    for (int kc = 0; kc < 4; ++kc) \
        B[kc] = *(const uint2*)&wb[(((Q)*4 + kc)*4 + kt)*32 + lane]; }

#define MMA4(AF) { d0 = d1 = d2 = d3 = 0.f; \
    mma8(d0,d1,d2,d3, AF[0][0],AF[0][1],AF[0][2],AF[0][3], B[0].x, B[0].y); \
    mma8(d0,d1,d2,d3, AF[1][0],AF[1][1],AF[1][2],AF[1][3], B[1].x, B[1].y); \
    mma8(d0,d1,d2,d3, AF[2][0],AF[2][1],AF[2][2],AF[2][3], B[2].x, B[2].y); \
    mma8(d0,d1,d2,d3, AF[3][0],AF[3][1],AF[3][2],AF[3][3], B[3].x, B[3].y); }

#define FOLD(CH, CL, CH_) { \
    acc[CH][0] += (CL)*d0; acc[CH][1] += (CL)*d1; \
    acc[CH][2] += (CH_)*d2; acc[CH][3] += (CH_)*d3; }

__global__ __launch_bounds__(THREADS, 2)
void td_mma(const float* __restrict__ x,
            const float* __restrict__ W1_0, const float* __restrict__ W1_1,
            const float* __restrict__ W2_0, const float* __restrict__ W2_1,
            float* __restrict__ out, int N)
{
    extern __shared__ float smem[];
    float2* wbuf = (float2*)smem;               // [2][3072]
    float4* Ash  = (float4*)(wbuf + 6144);      // [512]
    float4* Bsh  = Ash + 512;                   // [512]
    float*  xs   = smem;                        // prologue overlay

    const int tid = threadIdx.x;
    const int n0  = blockIdx.x * NPB;

    // ---- stage x rows ----
    for (int e = tid; e < NPB * 128; e += THREADS) {
        int node = e >> 7;
        xs[e] = (n0 + node < N) ? x[(size_t)(n0 + node) * 128 + (e & 127)] : 0.0f;
    }
    __syncthreads();

    // ---- prologue: A=(s@W1_0, v@W1_1), B=(s@W2_0, v@W2_1) ----
    for (int t = tid; t < NPB * 32 * 2; t += THREADS) {
        int which = (t >= NPB * 32);
        int tt = t & (NPB * 32 - 1);
        int node = tt >> 5, i = tt & 31;
        const float* Ws = which ? W2_0 : W1_0;
        const float* Wv = which ? W2_1 : W1_1;
        const float* xr = xs + node * 128;
        float s = 0.f, v0 = 0.f, v1 = 0.f, v2 = 0.f;
        #pragma unroll
        for (int m = 0; m < 32; ++m) {
            float ws = Ws[m * 32 + i];
            float wv = Wv[m * 32 + i];
            s  += xr[m] * ws;
            v0 += xr[32 + 3 * m + 0] * wv;
            v1 += xr[32 + 3 * m + 1] * wv;
            v2 += xr[32 + 3 * m + 2] * wv;
        }
        float4 r = make_float4(s, v0, v1, v2);
        if (which) Bsh[node * 32 + i] = r;
        else       Ash[node * 32 + i] = r;
    }
    __syncthreads();   // xs overlay fully consumed

    const unsigned sW = s2u(wbuf);
    // stage chunk 0
    {
        const char* src = (const char*)g_Wt;
        #pragma unroll
        for (int r = 0; r < 6; ++r) {
            int idx = tid + r * THREADS;
            cp16(sW + idx * 16, src + idx * 16);
        }
        cp_commit();
    }

    const int lane = tid & 31, wid = tid >> 5;
    const int kt = wid & 3, ih = wid >> 2;
    const int g = lane >> 2, tig = lane & 3;

    const float C0  = -0.57735026918962576f;
    const float C1  = -0.70710678118654752f;
    const float C2  =  0.70710678118654752f;
    const float C2z =  0.40824829046386302f;
    const int kbase = kt * 8 + 2 * tig;

    if (ih == 0) {
        // ---- pair-half 0: streams w0x,w0y,w1y,w1x -> m0..m7 -> acc0..acc4 ----
        unsigned af[4][4][4];   // [comp s,v0,v1,v2][kc][frag reg]
        #pragma unroll
        for (int kc = 0; kc < 4; ++kc) {
            float4 L0 = Bsh[g * 32 + kc * 8 + tig];
            float4 H0 = Bsh[(g + 8) * 32 + kc * 8 + tig];
            float4 L1 = Bsh[g * 32 + kc * 8 + tig + 4];
            float4 H1 = Bsh[(g + 8) * 32 + kc * 8 + tig + 4];
            af[0][kc][0]=f2tf(L0.x); af[0][kc][1]=f2tf(H0.x); af[0][kc][2]=f2tf(L1.x); af[0][kc][3]=f2tf(H1.x);
            af[1][kc][0]=f2tf(L0.y); af[1][kc][1]=f2tf(H0.y); af[1][kc][2]=f2tf(L1.y); af[1][kc][3]=f2tf(H1.y);
            af[2][kc][0]=f2tf(L0.z); af[2][kc][1]=f2tf(H0.z); af[2][kc][2]=f2tf(L1.z); af[2][kc][3]=f2tf(H1.z);
            af[3][kc][0]=f2tf(L0.w); af[3][kc][1]=f2tf(H0.w); af[3][kc][2]=f2tf(L1.w); af[3][kc][3]=f2tf(H1.w);
        }
        float acc[5][4];
        #pragma unroll
        for (int c = 0; c < 5; ++c) { acc[c][0]=acc[c][1]=acc[c][2]=acc[c][3]=0.f; }

        for (int i = 0; i < 32; ++i) {
            cp_wait0();
            barall();
            if (i + 1 < 32) {
                const char* src = (const char*)g_Wt + (i + 1) * 24576;
                unsigned dst = sW + ((i + 1) & 1) * 24576;
                #pragma unroll
                for (int r = 0; r < 6; ++r) {
                    int idx = tid + r * THREADS;
                    cp16(dst + idx * 16, src + idx * 16);
                }
            }
            cp_commit();

            const float2* wb = wbuf + (i & 1) * 3072;
            float4 AL = Ash[g * 32 + i];
            float4 AH = Ash[(g + 8) * 32 + i];
            uint2 B[4];
            float d0, d1, d2, d3;

            LDB(B, 0);                                  // w0x
            MMA4(af[0]); FOLD(0, AL.x, AH.x);           // m0 = w0x*s
            LDB(B, 1);                                  // w0y
            MMA4(af[1]); FOLD(1, AL.y, AH.y);           // m1
            MMA4(af[2]); FOLD(1, AL.z, AH.z);           // m2
            MMA4(af[3]); FOLD(1, AL.w, AH.w);           // m3
            LDB(B, 2);                                  // w1y
            MMA4(af[0]);                                // m7 = w1y*s
            FOLD(2, AL.y, AH.y); FOLD(3, AL.z, AH.z); FOLD(4, AL.w, AH.w);
            LDB(B, 3);                                  // w1x
            MMA4(af[1]); FOLD(2, AL.x, AH.x);           // m4
            MMA4(af[2]); FOLD(3, AL.x, AH.x);           // m5
            MMA4(af[3]); FOLD(4, AL.x, AH.x);           // m6
        }

        #pragma unroll
        for (int eh = 0; eh < 2; ++eh) {
            int node = n0 + (eh ? g + 8 : g);
            if (node >= N) continue;
            float* o = out + (size_t)node * 384;
            #pragma unroll
            for (int ec = 0; ec < 2; ++ec) {
                int e = eh * 2 + ec, c = kbase + ec;
                o[c] = acc[0][e] + C0 * acc[1][e];
                o[32 + 3 * c + 0] = acc[2][e];
                o[32 + 3 * c + 1] = acc[3][e];
                o[32 + 3 * c + 2] = acc[4][e];
            }
        }
    } else {
        // ---- pair-half 1: streams w2x,w2y -> m8..m13 -> acc5..acc12 (local 0..7) ----
        unsigned af[3][4][4];   // [comp v0,v1,v2][kc][frag]
        #pragma unroll
        for (int kc = 0; kc < 4; ++kc) {
            float4 L0 = Bsh[g * 32 + kc * 8 + tig];
            float4 H0 = Bsh[(g + 8) * 32 + kc * 8 + tig];
            float4 L1 = Bsh[g * 32 + kc * 8 + tig + 4];
            float4 H1 = Bsh[(g + 8) * 32 + kc * 8 + tig + 4];
            af[0][kc][0]=f2tf(L0.y); af[0][kc][1]=f2tf(H0.y); af[0][kc][2]=f2tf(L1.y); af[0][kc][3]=f2tf(H1.y);
            af[1][kc][0]=f2tf(L0.z); af[1][kc][1]=f2tf(H0.z); af[1][kc][2]=f2tf(L1.z); af[1][kc][3]=f2tf(H1.z);
            af[2][kc][0]=f2tf(L0.w); af[2][kc][1]=f2tf(H0.w); af[2][kc][2]=f2tf(L1.w); af[2][kc][3]=f2tf(H1.w);
        }
        float acc[8][4];
        #pragma unroll
        for (int c = 0; c < 8; ++c) { acc[c][0]=acc[c][1]=acc[c][2]=acc[c][3]=0.f; }

        for (int i = 0; i < 32; ++i) {
            cp_wait0();
            barall();
            if (i + 1 < 32) {
                const char* src = (const char*)g_Wt + (i + 1) * 24576;
                unsigned dst = sW + ((i + 1) & 1) * 24576;
                #pragma unroll
                for (int r = 0; r < 6; ++r) {
                    int idx = tid + r * THREADS;
                    cp16(dst + idx * 16, src + idx * 16);
                }
            }
            cp_commit();

            const float2* wb = wbuf + (i & 1) * 3072;
            float4 AL = Ash[g * 32 + i];
            float4 AH = Ash[(g + 8) * 32 + i];
            uint2 B[4];
            float d0, d1, d2, d3;

            LDB(B, 4);                                   // w2x
            MMA4(af[0]);                                 // m8
            FOLD(1,  AL.w,  AH.w);  FOLD(2, -AL.z, -AH.z);
            MMA4(af[1]);                                 // m9
            FOLD(2,  AL.y,  AH.y);  FOLD(0, -AL.w, -AH.w);
            MMA4(af[2]);                                 // m10
            FOLD(0,  AL.z,  AH.z);  FOLD(1, -AL.y, -AH.y);
            LDB(B, 5);                                   // w2y
            MMA4(af[0]);                                 // m11
            FOLD(3,  AL.w,  AH.w);  FOLD(4,  AL.z,  AH.z);
            FOLD(5, -AL.y, -AH.y);  FOLD(7, -AL.y, -AH.y);
            MMA4(af[1]);                                 // m12
            FOLD(4,  AL.y,  AH.y);  FOLD(5, 2.f*AL.z, 2.f*AH.z);
            FOLD(6,  AL.w,  AH.w);
            MMA4(af[2]);                                 // m13
            FOLD(3,  AL.y,  AH.y);  FOLD(5, -AL.w, -AH.w);
            FOLD(6,  AL.z,  AH.z);  FOLD(7,  AL.w,  AH.w);
        }

        #pragma unroll
        for (int eh = 0; eh < 2; ++eh) {
            int node = n0 + (eh ? g + 8 : g);
            if (node >= N) continue;
            float* o = out + (size_t)node * 384;
            #pragma unroll
            for (int ec = 0; ec < 2; ++ec) {
                int e = eh * 2 + ec, c = kbase + ec;
                o[128 + 3 * c + 0] = C1 * acc[0][e];
                o[128 + 3 * c + 1] = C1 * acc[1][e];
                o[128 + 3 * c + 2] = C1 * acc[2][e];
                o[224 + 5 * c + 0] = C2  * acc[3][e];
                o[224 + 5 * c + 1] = C2  * acc[4][e];
                o[224 + 5 * c + 2] = C2z * acc[5][e];
                o[224 + 5 * c + 3] = C2  * acc[6][e];
                o[224 + 5 * c + 4] = C2  * acc[7][e];
            }
        }
    }
}

extern "C" void kernel_launch(void* const* d_in, const int* in_sizes, int n_in,
                              void* d_out, int out_size)
{
    const float* x     = (const float*)d_in[0];
    const float* W1_0  = (const float*)d_in[1];
    const float* W1_1  = (const float*)d_in[2];
    const float* W2_0  = (const float*)d_in[3];
    const float* W2_1  = (const float*)d_in[4];
    const float* W3_0e = (const float*)d_in[5];
    const float* W3_1o = (const float*)d_in[6];
    const float* W3_1e = (const float*)d_in[7];
    const float* W3_2e = (const float*)d_in[8];

    int N = in_sizes[0] / 128;
    int blocks = (N + NPB - 1) / NPB;
    size_t smem = 6144 * sizeof(float2) + 1024 * sizeof(float4); // 64KB

    cudaFuncSetAttribute(td_mma, cudaFuncAttributeMaxDynamicSharedMemorySize,
                         (int)smem);

    pack_w<<<384, 256>>>(W3_0e, W3_1o, W3_1e, W3_2e);
    td_mma<<<blocks, THREADS, smem>>>(x, W1_0, W1_1, W2_0, W2_1,
                                      (float*)d_out, N);
}

// round 11
// speedup vs baseline: 3.9535x; 1.2820x over previous
#include <cuda_runtime.h>
#include <cuda_fp16.h>

#define NPB 16
#define THREADS 256

// Fragment-major fp16 weights, packed by pack_w every launch.
// g_Wt_h[(((i*6+q)*2+kc)*4+kt)*32 + lane] = uint2:
//   .x = h2( Wq[i*32 + kc*16 + 2*tig    ][kt*8+g], Wq[.. +2*tig+1][kt*8+g] )
//   .y = h2( Wq[i*32 + kc*16 + 2*tig + 8][kt*8+g], Wq[.. +2*tig+9][kt*8+g] )
// streams q: 0=w0x(W3_0e lo) 1=w0y(W3_0e hi) 2=w1y(W3_1o hi) 3=w1x(W3_1o lo)
//            4=w2x(W3_1e)    5=w2y(W3_2e)
__device__ __align__(16) uint2 g_Wt_h[49152];

__device__ __forceinline__ unsigned h2u(float a, float b) {
    __half2 h = __floats2half2_rn(a, b);
    return *(unsigned*)&h;
}
__device__ __forceinline__ void mma16(float& d0, float& d1, float& d2, float& d3,
                                      unsigned a0, unsigned a1, unsigned a2, unsigned a3,
                                      unsigned b0, unsigned b1) {
    asm volatile("mma.sync.aligned.m16n8k16.row.col.f32.f16.f16.f32 "
                 "{%0,%1,%2,%3}, {%4,%5,%6,%7}, {%8,%9}, {%0,%1,%2,%3};"
                 : "+f"(d0), "+f"(d1), "+f"(d2), "+f"(d3)
                 : "r"(a0), "r"(a1), "r"(a2), "r"(a3), "r"(b0), "r"(b1));
}
__device__ __forceinline__ unsigned s2u(const void* p) {
    return (unsigned)__cvta_generic_to_shared(p);
}
__device__ __forceinline__ void cp16(unsigned dst, const void* src) {
    asm volatile("cp.async.cg.shared.global [%0], [%1], 16;" :: "r"(dst), "l"(src));
}
__device__ __forceinline__ void cp_commit() {
    asm volatile("cp.async.commit_group;" ::: "memory");
}
__device__ __forceinline__ void cp_wait0() {
    asm volatile("cp.async.wait_group 0;" ::: "memory");
}
__device__ __forceinline__ void barall() {
    asm volatile("bar.sync 0, %0;" :: "n"(THREADS) : "memory");
}

__global__ void pack_w(const float* __restrict__ W3_0e, const float* __restrict__ W3_1o,
                       const float* __restrict__ W3_1e, const float* __restrict__ W3_2e)
{
    int t = blockIdx.x * blockDim.x + threadIdx.x;
    if (t >= 49152) return;
    int lane = t & 31, r = t >> 5;
    int kt = r & 3;  r >>= 2;
    int kc = r & 1;  r >>= 1;
    int q  = r % 6;
    int i  = r / 6;
    int g = lane >> 2, tig = lane & 3;
    int j0 = kc * 16 + 2 * tig;
    int n  = kt * 8 + g;
    const float* src; int off = 0;
    switch (q) {
        case 0: src = W3_0e; off = 0;     break;
        case 1: src = W3_0e; off = 32768; break;
        case 2: src = W3_1o; off = 32768; break;
        case 3: src = W3_1o; off = 0;     break;
        case 4: src = W3_1e; off = 0;     break;
        default: src = W3_2e; off = 0;    break;
    }
    uint2 w;
    w.x = h2u(src[off + (i * 32 + j0    ) * 32 + n], src[off + (i * 32 + j0 + 1) * 32 + n]);
    w.y = h2u(src[off + (i * 32 + j0 + 8) * 32 + n], src[off + (i * 32 + j0 + 9) * 32 + n]);
    g_Wt_h[t] = w;
}

// SMEM (dynamic, 40KB):
//   wbuf : uint2[2][1536]  24KB @0       (per-i fp16 weight fragments, dbl buffer)
//   Ash  : float4[512]      8KB @24KB
//   Bsh  : float4[512]      8KB @32KB
//   prologue overlays on wbuf: xs float[2048) @0 (8KB), Wsh float[2048..6144) (16KB)

#define LDB(Q) { \
    B0 = wb[(((Q) * 8) + kt) * 32 + lane]; \
    B1 = wb[(((Q) * 8) + 4 + kt) * 32 + lane]; }

#define MMA2(AF) { d0 = d1 = d2 = d3 = 0.f; \
    mma16(d0,d1,d2,d3, AF[0][0],AF[0][1],AF[0][2],AF[0][3], B0.x, B0.y); \
    mma16(d0,d1,d2,d3, AF[1][0],AF[1][1],AF[1][2],AF[1][3], B1.x, B1.y); }

#define FOLD(CH, CL, CH_) { \
    acc[CH][0] += (CL)*d0; acc[CH][1] += (CL)*d1; \
    acc[CH][2] += (CH_)*d2; acc[CH][3] += (CH_)*d3; }

__global__ __launch_bounds__(THREADS, 2)
void td_mma(const float* __restrict__ x,
            const float* __restrict__ W1_0, const float* __restrict__ W1_1,
            const float* __restrict__ W2_0, const float* __restrict__ W2_1,
            float* __restrict__ out, int N)
{
    extern __shared__ float smem[];
    float4* Ash = (float4*)(smem + 6144);       // [512]
    float4* Bsh = Ash + 512;                    // [512]
    float*  xs  = smem;                         // overlay [0..2048)

    const int tid = threadIdx.x;
    const int n0  = blockIdx.x * NPB;
    const unsigned sW = s2u(smem);

    // ---- async-stage W1_0,W1_1,W2_0,W2_1 into Wsh (16KB @ byte 8192) ----
    cp16(sW + 8192  + tid * 16, W1_0 + tid * 4);
    cp16(sW + 12288 + tid * 16, W1_1 + tid * 4);
    cp16(sW + 16384 + tid * 16, W2_0 + tid * 4);
    cp16(sW + 20480 + tid * 16, W2_1 + tid * 4);
    cp_commit();

    // ---- stage x rows (overlaps W cp) ----
    for (int e = tid; e < NPB * 128; e += THREADS) {
        int node = e >> 7;
        xs[e] = (n0 + node < N) ? x[(size_t)(n0 + node) * 128 + (e & 127)] : 0.0f;
    }
    cp_wait0();
    __syncthreads();

    // ---- prologue matvec from SMEM: A=(s@W1_0, v@W1_1), B=(s@W2_0, v@W2_1) ----
    for (int t = tid; t < NPB * 32 * 2; t += THREADS) {
        int which = (t >= NPB * 32);
        int tt = t & (NPB * 32 - 1);
        int node = tt >> 5, i = tt & 31;
        const float* Ws = smem + 2048 + which * 2048;
        const float* Wv = Ws + 1024;
        const float* xr = xs + node * 128;
        float s = 0.f, v0 = 0.f, v1 = 0.f, v2 = 0.f;
        #pragma unroll
        for (int m = 0; m < 32; ++m) {
            float ws = Ws[m * 32 + i];
            float wv = Wv[m * 32 + i];
            s  += xr[m] * ws;
            v0 += xr[32 + 3 * m + 0] * wv;
            v1 += xr[32 + 3 * m + 1] * wv;
            v2 += xr[32 + 3 * m + 2] * wv;
        }
        float4 r = make_float4(s, v0, v1, v2);
        if (which) Bsh[node * 32 + i] = r;
        else       Ash[node * 32 + i] = r;
    }
    __syncthreads();   // overlays dead; Ash/Bsh live

    // ---- stage weight chunk 0 (12KB) ----
    #pragma unroll
    for (int r = 0; r < 3; ++r) {
        int idx = tid + r * THREADS;
        cp16(sW + idx * 16, (const char*)g_Wt_h + idx * 16);
    }
    cp_commit();

    const int lane = tid & 31, wid = tid >> 5;
    const int kt = wid & 3, ih = wid >> 2;
    const int g = lane >> 2, tig = lane & 3;

    const float C0  = -0.57735026918962576f;
    const float C1  = -0.70710678118654752f;
    const float C2  =  0.70710678118654752f;
    const float C2z =  0.40824829046386302f;
    const int kbase = kt * 8 + 2 * tig;

    if (ih == 0) {
        // ---- half 0: streams w0x,w0y,w1y,w1x -> m0..m7 ----
        unsigned af[4][2][4];   // [comp s,v0,v1,v2][kc][frag]
        #pragma unroll
        for (int kc = 0; kc < 2; ++kc) {
            int jb = kc * 16 + 2 * tig;
            float4 P0 = Bsh[g * 32 + jb],           P1 = Bsh[g * 32 + jb + 1];
            float4 Q0 = Bsh[(g + 8) * 32 + jb],     Q1 = Bsh[(g + 8) * 32 + jb + 1];
            float4 R0 = Bsh[g * 32 + jb + 8],       R1 = Bsh[g * 32 + jb + 9];
            float4 S0 = Bsh[(g + 8) * 32 + jb + 8], S1 = Bsh[(g + 8) * 32 + jb + 9];
            af[0][kc][0]=h2u(P0.x,P1.x); af[0][kc][1]=h2u(Q0.x,Q1.x); af[0][kc][2]=h2u(R0.x,R1.x); af[0][kc][3]=h2u(S0.x,S1.x);
            af[1][kc][0]=h2u(P0.y,P1.y); af[1][kc][1]=h2u(Q0.y,Q1.y); af[1][kc][2]=h2u(R0.y,R1.y); af[1][kc][3]=h2u(S0.y,S1.y);
            af[2][kc][0]=h2u(P0.z,P1.z); af[2][kc][1]=h2u(Q0.z,Q1.z); af[2][kc][2]=h2u(R0.z,R1.z); af[2][kc][3]=h2u(S0.z,S1.z);
            af[3][kc][0]=h2u(P0.w,P1.w); af[3][kc][1]=h2u(Q0.w,Q1.w); af[3][kc][2]=h2u(R0.w,R1.w); af[3][kc][3]=h2u(S0.w,S1.w);
        }
        float acc[5][4];
        #pragma unroll
        for (int c = 0; c < 5; ++c) { acc[c][0]=acc[c][1]=acc[c][2]=acc[c][3]=0.f; }

        for (int i = 0; i < 32; ++i) {
            cp_wait0();
            barall();
            if (i + 1 < 32) {
                const char* src = (const char*)g_Wt_h + (i + 1) * 12288;
                unsigned dst = sW + ((i + 1) & 1) * 12288;
                #pragma unroll
                for (int r = 0; r < 3; ++r) {
                    int idx = tid + r * THREADS;
                    cp16(dst + idx * 16, src + idx * 16);
                }
            }
            cp_commit();

            const uint2* wb = (const uint2*)((const char*)smem + (i & 1) * 12288);
            float4 AL = Ash[g * 32 + i];
            float4 AH = Ash[(g + 8) * 32 + i];
            uint2 B0, B1;
            float d0, d1, d2, d3;

            LDB(0);                                   // w0x
            MMA2(af[0]); FOLD(0, AL.x, AH.x);         // m0
            LDB(1);                                   // w0y
            MMA2(af[1]); FOLD(1, AL.y, AH.y);         // m1
            MMA2(af[2]); FOLD(1, AL.z, AH.z);         // m2
            MMA2(af[3]); FOLD(1, AL.w, AH.w);         // m3
            LDB(2);                                   // w1y
            MMA2(af[0]);                              // m7
            FOLD(2, AL.y, AH.y); FOLD(3, AL.z, AH.z); FOLD(4, AL.w, AH.w);
            LDB(3);                                   // w1x
            MMA2(af[1]); FOLD(2, AL.x, AH.x);         // m4
            MMA2(af[2]); FOLD(3, AL.x, AH.x);         // m5
            MMA2(af[3]); FOLD(4, AL.x, AH.x);         // m6
        }

        #pragma unroll
        for (int eh = 0; eh < 2; ++eh) {
            int node = n0 + (eh ? g + 8 : g);
            if (node >= N) continue;
            float* o = out + (size_t)node * 384;
            #pragma unroll
            for (int ec = 0; ec < 2; ++ec) {
                int e = eh * 2 + ec, c = kbase + ec;
                o[c] = acc[0][e] + C0 * acc[1][e];
                o[32 + 3 * c + 0] = acc[2][e];
                o[32 + 3 * c + 1] = acc[3][e];
                o[32 + 3 * c + 2] = acc[4][e];
            }
        }
    } else {
        // ---- half 1: streams w2x,w2y -> m8..m13 ----
        unsigned af[3][2][4];   // [comp v0,v1,v2][kc][frag]
        #pragma unroll
        for (int kc = 0; kc < 2; ++kc) {
            int jb = kc * 16 + 2 * tig;
            float4 P0 = Bsh[g * 32 + jb],           P1 = Bsh[g * 32 + jb + 1];
            float4 Q0 = Bsh[(g + 8) * 32 + jb],     Q1 = Bsh[(g + 8) * 32 + jb + 1];
            float4 R0 = Bsh[g * 32 + jb + 8],       R1 = Bsh[g * 32 + jb + 9];
            float4 S0 = Bsh[(g + 8) * 32 + jb + 8], S1 = Bsh[(g + 8) * 32 + jb + 9];
            af[0][kc][0]=h2u(P0.y,P1.y); af[0][kc][1]=h2u(Q0.y,Q1.y); af[0][kc][2]=h2u(R0.y,R1.y); af[0][kc][3]=h2u(S0.y,S1.y);
            af[1][kc][0]=h2u(P0.z,P1.z); af[1][kc][1]=h2u(Q0.z,Q1.z); af[1][kc][2]=h2u(R0.z,R1.z); af[1][kc][3]=h2u(S0.z,S1.z);
            af[2][kc][0]=h2u(P0.w,P1.w); af[2][kc][1]=h2u(Q0.w,Q1.w); af[2][kc][2]=h2u(R0.w,R1.w); af[2][kc][3]=h2u(S0.w,S1.w);
        }
        float acc[8][4];
        #pragma unroll
        for (int c = 0; c < 8; ++c) { acc[c][0]=acc[c][1]=acc[c][2]=acc[c][3]=0.f; }

        for (int i = 0; i < 32; ++i) {
            cp_wait0();
            barall();
            if (i + 1 < 32) {
                const char* src = (const char*)g_Wt_h + (i + 1) * 12288;
                unsigned dst = sW + ((i + 1) & 1) * 12288;
                #pragma unroll
                for (int r = 0; r < 3; ++r) {
                    int idx = tid + r * THREADS;
                    cp16(dst + idx * 16, src + idx * 16);
                }
            }
            cp_commit();

            const uint2* wb = (const uint2*)((const char*)smem + (i & 1) * 12288);
            float4 AL = Ash[g * 32 + i];
            float4 AH = Ash[(g + 8) * 32 + i];
            uint2 B0, B1;
            float d0, d1, d2, d3;

            LDB(4);                                    // w2x
            MMA2(af[0]);                               // m8
            FOLD(1,  AL.w,  AH.w);  FOLD(2, -AL.z, -AH.z);
            MMA2(af[1]);                               // m9
            FOLD(2,  AL.y,  AH.y);  FOLD(0, -AL.w, -AH.w);
            MMA2(af[2]);                               // m10
            FOLD(0,  AL.z,  AH.z);  FOLD(1, -AL.y, -AH.y);
            LDB(5);                                    // w2y
            MMA2(af[0]);                               // m11
            FOLD(3,  AL.w,  AH.w);  FOLD(4,  AL.z,  AH.z);
            FOLD(5, -AL.y, -AH.y);  FOLD(7, -AL.y, -AH.y);
            MMA2(af[1]);                               // m12
            FOLD(4,  AL.y,  AH.y);  FOLD(5, 2.f*AL.z, 2.f*AH.z);
            FOLD(6,  AL.w,  AH.w);
            MMA2(af[2]);                               // m13
            FOLD(3,  AL.y,  AH.y);  FOLD(5, -AL.w, -AH.w);
            FOLD(6,  AL.z,  AH.z);  FOLD(7,  AL.w,  AH.w);
        }

        #pragma unroll
        for (int eh = 0; eh < 2; ++eh) {
            int node = n0 + (eh ? g + 8 : g);
            if (node >= N) continue;
            float* o = out + (size_t)node * 384;
            #pragma unroll
            for (int ec = 0; ec < 2; ++ec) {
                int e = eh * 2 + ec, c = kbase + ec;
                o[128 + 3 * c + 0] = C1 * acc[0][e];
                o[128 + 3 * c + 1] = C1 * acc[1][e];
                o[128 + 3 * c + 2] = C1 * acc[2][e];
                o[224 + 5 * c + 0] = C2  * acc[3][e];
                o[224 + 5 * c + 1] = C2  * acc[4][e];
                o[224 + 5 * c + 2] = C2z * acc[5][e];
                o[224 + 5 * c + 3] = C2  * acc[6][e];
                o[224 + 5 * c + 4] = C2  * acc[7][e];
            }
        }
    }
}

extern "C" void kernel_launch(void* const* d_in, const int* in_sizes, int n_in,
                              void* d_out, int out_size)
{
    const float* x     = (const float*)d_in[0];
    const float* W1_0  = (const float*)d_in[1];
    const float* W1_1  = (const float*)d_in[2];
    const float* W2_0  = (const float*)d_in[3];
    const float* W2_1  = (const float*)d_in[4];
    const float* W3_0e = (const float*)d_in[5];
    const float* W3_1o = (const float*)d_in[6];
    const float* W3_1e = (const float*)d_in[7];
    const float* W3_2e = (const float*)d_in[8];

    int N = in_sizes[0] / 128;
    int blocks = (N + NPB - 1) / NPB;
    size_t smem = 2 * 1536 * sizeof(uint2) + 1024 * sizeof(float4); // 40KB

    cudaFuncSetAttribute(td_mma, cudaFuncAttributeMaxDynamicSharedMemorySize,
                         (int)smem);

    pack_w<<<192, 256>>>(W3_0e, W3_1o, W3_1e, W3_2e);
    td_mma<<<blocks, THREADS, smem>>>(x, W1_0, W1_1, W2_0, W2_1,
                                      (float*)d_out, N);
}

// round 12
// speedup vs baseline: 4.0821x; 1.0325x over previous
#include <cuda_runtime.h>
#include <cuda_fp16.h>

#define NPB 32
#define THREADS 256

// Fragment-major fp16 weights, packed by pack_w every launch.
// g_Wt_h[(((i*6+q)*2+kc)*4+kt)*32 + lane], streams q:
// 0=w0x(W3_0e lo) 1=w0y(W3_0e hi) 2=w1y(W3_1o hi) 3=w1x(W3_1o lo) 4=w2x(W3_1e) 5=w2y(W3_2e)
__device__ __align__(16) uint2 g_Wt_h[49152];

__device__ __forceinline__ unsigned h2u(float a, float b) {
    __half2 h = __floats2half2_rn(a, b);
    return *(unsigned*)&h;
}
__device__ __forceinline__ void mma16(float& d0, float& d1, float& d2, float& d3,
                                      unsigned a0, unsigned a1, unsigned a2, unsigned a3,
                                      unsigned b0, unsigned b1) {
    asm volatile("mma.sync.aligned.m16n8k16.row.col.f32.f16.f16.f32 "
                 "{%0,%1,%2,%3}, {%4,%5,%6,%7}, {%8,%9}, {%0,%1,%2,%3};"
                 : "+f"(d0), "+f"(d1), "+f"(d2), "+f"(d3)
                 : "r"(a0), "r"(a1), "r"(a2), "r"(a3), "r"(b0), "r"(b1));
}
__device__ __forceinline__ unsigned s2u(const void* p) {
    return (unsigned)__cvta_generic_to_shared(p);
}
__device__ __forceinline__ void cp16(unsigned dst, const void* src) {
    asm volatile("cp.async.cg.shared.global [%0], [%1], 16;" :: "r"(dst), "l"(src));
}
__device__ __forceinline__ void cp_commit() {
    asm volatile("cp.async.commit_group;" ::: "memory");
}
__device__ __forceinline__ void cp_wait0() {
    asm volatile("cp.async.wait_group 0;" ::: "memory");
}
__device__ __forceinline__ void barall() {
    asm volatile("bar.sync 0, %0;" :: "n"(THREADS) : "memory");
}

__global__ void pack_w(const float* __restrict__ W3_0e, const float* __restrict__ W3_1o,
                       const float* __restrict__ W3_1e, const float* __restrict__ W3_2e)
{
    int t = blockIdx.x * blockDim.x + threadIdx.x;
    if (t >= 49152) return;
    int lane = t & 31, r = t >> 5;
    int kt = r & 3;  r >>= 2;
    int kc = r & 1;  r >>= 1;
    int q  = r % 6;
    int i  = r / 6;
    int g = lane >> 2, tig = lane & 3;
    int j0 = kc * 16 + 2 * tig;
    int n  = kt * 8 + g;
    const float* src; int off = 0;
    switch (q) {
        case 0: src = W3_0e; off = 0;     break;
        case 1: src = W3_0e; off = 32768; break;
        case 2: src = W3_1o; off = 32768; break;
        case 3: src = W3_1o; off = 0;     break;
        case 4: src = W3_1e; off = 0;     break;
        default: src = W3_2e; off = 0;    break;
    }
    uint2 w;
    w.x = h2u(src[off + (i * 32 + j0    ) * 32 + n], src[off + (i * 32 + j0 + 1) * 32 + n]);
    w.y = h2u(src[off + (i * 32 + j0 + 8) * 32 + n], src[off + (i * 32 + j0 + 9) * 32 + n]);
    g_Wt_h[t] = w;
}

// SMEM (dynamic, 64KB):
//   wbuf: uint2[2][1536]   24KB @0       (per-i fp16 weight fragments, dbl buffer)
//   (8KB hole @24KB, prologue-only)
//   Ash : float4[1024]     16KB @32KB    (32 nodes)
//   Bsh : float4[1024]     16KB @48KB
//   prologue overlays: xs float[4096] @0 (16KB), Wsh float[4096] @16KB (16KB)

#define LDB(Q) { \
    B0 = wb[(((Q) * 8) + kt) * 32 + lane]; \
    B1 = wb[(((Q) * 8) + 4 + kt) * 32 + lane]; }

#define MMA2(AF) { d0 = d1 = d2 = d3 = 0.f; \
    mma16(d0,d1,d2,d3, AF[0][0],AF[0][1],AF[0][2],AF[0][3], B0.x, B0.y); \
    mma16(d0,d1,d2,d3, AF[1][0],AF[1][1],AF[1][2],AF[1][3], B1.x, B1.y); }

#define FOLD(CH, CL, CH_) { \
    acc[CH][0] += (CL)*d0; acc[CH][1] += (CL)*d1; \
    acc[CH][2] += (CH_)*d2; acc[CH][3] += (CH_)*d3; }

__global__ __launch_bounds__(THREADS, 2)
void td_mma(const float* __restrict__ x,
            const float* __restrict__ W1_0, const float* __restrict__ W1_1,
            const float* __restrict__ W2_0, const float* __restrict__ W2_1,
            float* __restrict__ out, int N)
{
    extern __shared__ float smem[];
    float4* Ash = (float4*)((char*)smem + 32768);   // [1024]
    float4* Bsh = (float4*)((char*)smem + 49152);   // [1024]
    float*  xs  = smem;                             // overlay [0..4096)
    float*  Wsh = smem + 4096;                      // overlay [4096..8192)

    const int tid = threadIdx.x;
    const int n0  = blockIdx.x * NPB;
    const unsigned sW = s2u(smem);

    // ---- async-stage W1_0,W1_1,W2_0,W2_1 into Wsh (16KB @ byte 16384) ----
    cp16(sW + 16384 + tid * 16, W1_0 + tid * 4);
    cp16(sW + 20480 + tid * 16, W1_1 + tid * 4);
    cp16(sW + 24576 + tid * 16, W2_0 + tid * 4);
    cp16(sW + 28672 + tid * 16, W2_1 + tid * 4);
    cp_commit();

    // ---- stage x rows (overlaps W cp) ----
    for (int e = tid; e < NPB * 128; e += THREADS) {
        int node = e >> 7;
        xs[e] = (n0 + node < N) ? x[(size_t)(n0 + node) * 128 + (e & 127)] : 0.0f;
    }
    cp_wait0();
    __syncthreads();

    // ---- prologue matvec: A=(s@W1_0, v@W1_1), B=(s@W2_0, v@W2_1) ----
    for (int t = tid; t < NPB * 32 * 2; t += THREADS) {
        int which = (t >= NPB * 32);
        int tt = t & (NPB * 32 - 1);
        int node = tt >> 5, i = tt & 31;
        const float* Ws = Wsh + which * 2048;
        const float* Wv = Ws + 1024;
        const float* xr = xs + node * 128;
        float s = 0.f, v0 = 0.f, v1 = 0.f, v2 = 0.f;
        #pragma unroll
        for (int m = 0; m < 32; ++m) {
            float ws = Ws[m * 32 + i];
            float wv = Wv[m * 32 + i];
            s  += xr[m] * ws;
            v0 += xr[32 + 3 * m + 0] * wv;
            v1 += xr[32 + 3 * m + 1] * wv;
            v2 += xr[32 + 3 * m + 2] * wv;
        }
        float4 r = make_float4(s, v0, v1, v2);
        if (which) Bsh[node * 32 + i] = r;
        else       Ash[node * 32 + i] = r;
    }
    __syncthreads();   // overlays dead; Ash/Bsh live

    // ---- stage weight chunk 0 (12KB) ----
    #pragma unroll
    for (int r = 0; r < 3; ++r) {
        int idx = tid + r * THREADS;
        cp16(sW + idx * 16, (const char*)g_Wt_h + idx * 16);
    }
    cp_commit();

    const int lane = tid & 31, wid = tid >> 5;
    const int tile = wid & 1, kt = wid >> 1;
    const int g = lane >> 2, tig = lane & 3;
    const int tb = tile * 16;

    // ---- A-operand fragments (all 4 components; built once) ----
    unsigned af[4][2][4];
    #pragma unroll
    for (int kc = 0; kc < 2; ++kc) {
        int jb = kc * 16 + 2 * tig;
        float4 P0 = Bsh[(tb + g) * 32 + jb],         P1 = Bsh[(tb + g) * 32 + jb + 1];
        float4 Q0 = Bsh[(tb + g + 8) * 32 + jb],     Q1 = Bsh[(tb + g + 8) * 32 + jb + 1];
        float4 R0 = Bsh[(tb + g) * 32 + jb + 8],     R1 = Bsh[(tb + g) * 32 + jb + 9];
        float4 S0 = Bsh[(tb + g + 8) * 32 + jb + 8], S1 = Bsh[(tb + g + 8) * 32 + jb + 9];
        af[0][kc][0]=h2u(P0.x,P1.x); af[0][kc][1]=h2u(Q0.x,Q1.x); af[0][kc][2]=h2u(R0.x,R1.x); af[0][kc][3]=h2u(S0.x,S1.x);
        af[1][kc][0]=h2u(P0.y,P1.y); af[1][kc][1]=h2u(Q0.y,Q1.y); af[1][kc][2]=h2u(R0.y,R1.y); af[1][kc][3]=h2u(S0.y,S1.y);
        af[2][kc][0]=h2u(P0.z,P1.z); af[2][kc][1]=h2u(Q0.z,Q1.z); af[2][kc][2]=h2u(R0.z,R1.z); af[2][kc][3]=h2u(S0.z,S1.z);
        af[3][kc][0]=h2u(P0.w,P1.w); af[3][kc][1]=h2u(Q0.w,Q1.w); af[3][kc][2]=h2u(R0.w,R1.w); af[3][kc][3]=h2u(S0.w,S1.w);
    }

    float acc[13][4];
    #pragma unroll
    for (int c = 0; c < 13; ++c) { acc[c][0]=acc[c][1]=acc[c][2]=acc[c][3]=0.f; }

    for (int i = 0; i < 32; ++i) {
        cp_wait0();
        barall();
        if (i + 1 < 32) {
            const char* src = (const char*)g_Wt_h + (i + 1) * 12288;
            unsigned dst = sW + ((i + 1) & 1) * 12288;
            #pragma unroll
            for (int r = 0; r < 3; ++r) {
                int idx = tid + r * THREADS;
                cp16(dst + idx * 16, src + idx * 16);
            }
        }
        cp_commit();

        const uint2* wb = (const uint2*)((const char*)smem + (i & 1) * 12288);
        float4 AL = Ash[(tb + g) * 32 + i];
        float4 AH = Ash[(tb + g + 8) * 32 + i];
        uint2 B0, B1;
        float d0, d1, d2, d3;

        LDB(0);                                   // w0x
        MMA2(af[0]); FOLD(0, AL.x, AH.x);         // m0
        LDB(1);                                   // w0y
        MMA2(af[1]); FOLD(1, AL.y, AH.y);         // m1
        MMA2(af[2]); FOLD(1, AL.z, AH.z);         // m2
        MMA2(af[3]); FOLD(1, AL.w, AH.w);         // m3
        LDB(2);                                   // w1y
        MMA2(af[0]);                              // m7
        FOLD(2, AL.y, AH.y); FOLD(3, AL.z, AH.z); FOLD(4, AL.w, AH.w);
        LDB(3);                                   // w1x
        MMA2(af[1]); FOLD(2, AL.x, AH.x);         // m4
        MMA2(af[2]); FOLD(3, AL.x, AH.x);         // m5
        MMA2(af[3]); FOLD(4, AL.x, AH.x);         // m6
        LDB(4);                                   // w2x
        MMA2(af[1]);                              // m8
        FOLD(6,  AL.w,  AH.w);  FOLD(7, -AL.z, -AH.z);
        MMA2(af[2]);                              // m9
        FOLD(7,  AL.y,  AH.y);  FOLD(5, -AL.w, -AH.w);
        MMA2(af[3]);                              // m10
        FOLD(5,  AL.z,  AH.z);  FOLD(6, -AL.y, -AH.y);
        LDB(5);                                   // w2y
        MMA2(af[1]);                              // m11
        FOLD(8,  AL.w,  AH.w);  FOLD(9,  AL.z,  AH.z);
        FOLD(10, -AL.y, -AH.y); FOLD(12, -AL.y, -AH.y);
        MMA2(af[2]);                              // m12
        FOLD(9,  AL.y,  AH.y);  FOLD(10, 2.f*AL.z, 2.f*AH.z);
        FOLD(11, AL.w,  AH.w);
        MMA2(af[3]);                              // m13
        FOLD(8,  AL.y,  AH.y);  FOLD(10, -AL.w, -AH.w);
        FOLD(11, AL.z,  AH.z);  FOLD(12,  AL.w,  AH.w);
    }

    // ---- outputs ----
    const float C0  = -0.57735026918962576f;
    const float C1  = -0.70710678118654752f;
    const float C2  =  0.70710678118654752f;
    const float C2z =  0.40824829046386302f;
    const int kbase = kt * 8 + 2 * tig;

    #pragma unroll
    for (int eh = 0; eh < 2; ++eh) {
        int node = n0 + tb + (eh ? g + 8 : g);
        if (node >= N) continue;
        float* o = out + (size_t)node * 384;
        #pragma unroll
        for (int ec = 0; ec < 2; ++ec) {
            int e = eh * 2 + ec, c = kbase + ec;
            o[c] = acc[0][e] + C0 * acc[1][e];
            o[32  + 3 * c + 0] = acc[2][e];
            o[32  + 3 * c + 1] = acc[3][e];
            o[32  + 3 * c + 2] = acc[4][e];
            o[128 + 3 * c + 0] = C1 * acc[5][e];
            o[128 + 3 * c + 1] = C1 * acc[6][e];
            o[128 + 3 * c + 2] = C1 * acc[7][e];
            o[224 + 5 * c + 0] = C2  * acc[8][e];
            o[224 + 5 * c + 1] = C2  * acc[9][e];
            o[224 + 5 * c + 2] = C2z * acc[10][e];
            o[224 + 5 * c + 3] = C2  * acc[11][e];
            o[224 + 5 * c + 4] = C2  * acc[12][e];
        }
    }
}

extern "C" void kernel_launch(void* const* d_in, const int* in_sizes, int n_in,
                              void* d_out, int out_size)
{
    const float* x     = (const float*)d_in[0];
    const float* W1_0  = (const float*)d_in[1];
    const float* W1_1  = (const float*)d_in[2];
    const float* W2_0  = (const float*)d_in[3];
    const float* W2_1  = (const float*)d_in[4];
    const float* W3_0e = (const float*)d_in[5];
    const float* W3_1o = (const float*)d_in[6];
    const float* W3_1e = (const float*)d_in[7];
    const float* W3_2e = (const float*)d_in[8];

    int N = in_sizes[0] / 128;
    int blocks = (N + NPB - 1) / NPB;
    size_t smem = 65536;   // 64KB (weights dbuf + hole + Ash + Bsh; prologue overlays)

    cudaFuncSetAttribute(td_mma, cudaFuncAttributeMaxDynamicSharedMemorySize,
                         (int)smem);

    pack_w<<<192, 256>>>(W3_0e, W3_1o, W3_1e, W3_2e);
    td_mma<<<blocks, THREADS, smem>>>(x, W1_0, W1_1, W2_0, W2_1,
                                      (float*)d_out, N);
}

// round 14
// speedup vs baseline: 4.0990x; 1.0041x over previous
#include <cuda_runtime.h>
#include <cuda_fp16.h>

#define NPB 32
#define THREADS 256

// Fragment-major fp16 weights (packed by pack_w every launch).
// g_WtA[(((i*4+q)*2+kc)*4+kt)*32+lane], qA: 0=w0x 1=w0y 2=w1y 3=w1x   (8KB per i)
// g_WtB[(((i*2+qq)*2+kc)*4+kt)*32+lane], qq: 0=w2x(W3_1e) 1=w2y(W3_2e) (4KB per i)
__device__ __align__(16) uint2 g_WtA[32768];
__device__ __align__(16) uint2 g_WtB[16384];

__device__ __forceinline__ unsigned h2u(float a, float b) {
    __half2 h = __floats2half2_rn(a, b);
    return *(unsigned*)&h;
}
__device__ __forceinline__ void mma16(float& d0, float& d1, float& d2, float& d3,
                                      unsigned a0, unsigned a1, unsigned a2, unsigned a3,
                                      unsigned b0, unsigned b1) {
    asm volatile("mma.sync.aligned.m16n8k16.row.col.f32.f16.f16.f32 "
                 "{%0,%1,%2,%3}, {%4,%5,%6,%7}, {%8,%9}, {%0,%1,%2,%3};"
                 : "+f"(d0), "+f"(d1), "+f"(d2), "+f"(d3)
                 : "r"(a0), "r"(a1), "r"(a2), "r"(a3), "r"(b0), "r"(b1));
}
__device__ __forceinline__ unsigned s2u(const void* p) {
    return (unsigned)__cvta_generic_to_shared(p);
}
__device__ __forceinline__ void cp16(unsigned dst, const void* src) {
    asm volatile("cp.async.cg.shared.global [%0], [%1], 16;" :: "r"(dst), "l"(src));
}
__device__ __forceinline__ void cp_commit() {
    asm volatile("cp.async.commit_group;" ::: "memory");
}
__device__ __forceinline__ void cp_wait0() {
    asm volatile("cp.async.wait_group 0;" ::: "memory");
}
__device__ __forceinline__ void barall() {
    asm volatile("bar.sync 0, %0;" :: "n"(THREADS) : "memory");
}

__global__ void pack_w(const float* __restrict__ W3_0e, const float* __restrict__ W3_1o,
                       const float* __restrict__ W3_1e, const float* __restrict__ W3_2e)
{
    int t = blockIdx.x * blockDim.x + threadIdx.x;
    if (t >= 49152) return;
    int lane = t & 31;
    int g = lane >> 2, tig = lane & 3;
    if (t < 32768) {
        int r = t >> 5;
        int kt = r & 3;  r >>= 2;
        int kc = r & 1;  r >>= 1;
        int q  = r & 3;
        int i  = r >> 2;
        int j0 = kc * 16 + 2 * tig;
        int n  = kt * 8 + g;
        const float* src; int off = 0;
        switch (q) {
            case 0: src = W3_0e; off = 0;     break;
            case 1: src = W3_0e; off = 32768; break;
            case 2: src = W3_1o; off = 32768; break;
            default: src = W3_1o; off = 0;    break;
        }
        uint2 w;
        w.x = h2u(src[off + (i*32 + j0    )*32 + n], src[off + (i*32 + j0 + 1)*32 + n]);
        w.y = h2u(src[off + (i*32 + j0 + 8)*32 + n], src[off + (i*32 + j0 + 9)*32 + n]);
        g_WtA[t] = w;
    } else {
        int t2 = t - 32768;
        int r = t2 >> 5;
        int kt = r & 3;  r >>= 2;
        int kc = r & 1;  r >>= 1;
        int qq = r & 1;
        int i  = r >> 1;
        int j0 = kc * 16 + 2 * tig;
        int n  = kt * 8 + g;
        const float* src = qq ? W3_2e : W3_1e;
        uint2 w;
        w.x = h2u(src[(i*32 + j0    )*32 + n], src[(i*32 + j0 + 1)*32 + n]);
        w.y = h2u(src[(i*32 + j0 + 8)*32 + n], src[(i*32 + j0 + 9)*32 + n]);
        g_WtB[t2] = w;
    }
}

// SMEM (64KB):
//   wbufA: [0, 16K)      2 x 8KB double buffer (pass A weights)
//   wbufB: [16K, 24K)    2 x 4KB double buffer (pass B weights)
//   hole : [24K, 32K)
//   Ash  : [32K, 48K)    float4[1024]
//   Bsh  : [48K, 64K)    float4[1024]
//   prologue overlays: xs [0,16K), Wsh [16K,32K)

#define LDB(Q, X0, X1) { \
    X0 = wb[((Q) * 8 + kt) * 32 + lane]; \
    X1 = wb[((Q) * 8 + 4 + kt) * 32 + lane]; }

#define MMA2(AF, P, X0, X1) { \
    dd[P][0]=dd[P][1]=dd[P][2]=dd[P][3]=0.f; \
    mma16(dd[P][0],dd[P][1],dd[P][2],dd[P][3], AF[0][0],AF[0][1],AF[0][2],AF[0][3], X0.x, X0.y); \
    mma16(dd[P][0],dd[P][1],dd[P][2],dd[P][3], AF[1][0],AF[1][1],AF[1][2],AF[1][3], X1.x, X1.y); }

#define FOLDP(P, CH, CL, CH_) { \
    acc[CH][0] += (CL)*dd[P][0]; acc[CH][1] += (CL)*dd[P][1]; \
    acc[CH][2] += (CH_)*dd[P][2]; acc[CH][3] += (CH_)*dd[P][3]; }

__global__ __launch_bounds__(THREADS, 2)
void td_mma(const float* __restrict__ x,
            const float* __restrict__ W1_0, const float* __restrict__ W1_1,
            const float* __restrict__ W2_0, const float* __restrict__ W2_1,
            float* __restrict__ out, int N)
{
    extern __shared__ float smem[];
    float4* Ash = (float4*)((char*)smem + 32768);   // [1024]
    float4* Bsh = (float4*)((char*)smem + 49152);   // [1024]
    float*  xs  = smem;                             // overlay [0..4096)
    float*  Wsh = smem + 4096;                      // overlay [4096..8192)

    const int tid = threadIdx.x;
    const int n0  = blockIdx.x * NPB;
    const unsigned sWA = s2u(smem);
    const unsigned sWB = sWA + 16384;

    // ---- async-stage W1_0,W1_1,W2_0,W2_1 into Wsh ----
    cp16(sWA + 16384 + tid * 16, W1_0 + tid * 4);
    cp16(sWA + 20480 + tid * 16, W1_1 + tid * 4);
    cp16(sWA + 24576 + tid * 16, W2_0 + tid * 4);
    cp16(sWA + 28672 + tid * 16, W2_1 + tid * 4);
    cp_commit();

    // ---- stage x rows (overlaps W cp) ----
    for (int e = tid; e < NPB * 128; e += THREADS) {
        int node = e >> 7;
        xs[e] = (n0 + node < N) ? x[(size_t)(n0 + node) * 128 + (e & 127)] : 0.0f;
    }
    cp_wait0();
    __syncthreads();

    // ---- prologue matvec: A=(s@W1_0, v@W1_1), B=(s@W2_0, v@W2_1) ----
    for (int t = tid; t < NPB * 32 * 2; t += THREADS) {
        int which = (t >= NPB * 32);
        int tt = t & (NPB * 32 - 1);
        int node = tt >> 5, i = tt & 31;
        const float* Ws = Wsh + which * 2048;
        const float* Wv = Ws + 1024;
        const float* xr = xs + node * 128;
        float s = 0.f, v0 = 0.f, v1 = 0.f, v2 = 0.f;
        #pragma unroll
        for (int m = 0; m < 32; ++m) {
            float ws = Ws[m * 32 + i];
            float wv = Wv[m * 32 + i];
            s  += xr[m] * ws;
            v0 += xr[32 + 3 * m + 0] * wv;
            v1 += xr[32 + 3 * m + 1] * wv;
            v2 += xr[32 + 3 * m + 2] * wv;
        }
        float4 r = make_float4(s, v0, v1, v2);
        if (which) Bsh[node * 32 + i] = r;
        else       Ash[node * 32 + i] = r;
    }
    __syncthreads();   // overlays dead

    // ---- stage pass-A chunk 0 (8KB) and pass-B chunk 0 (4KB) ----
    {
        cp16(sWA + tid * 16, (const char*)g_WtA + tid * 16);
        cp16(sWA + 4096 + tid * 16, (const char*)g_WtA + 4096 + tid * 16);
        cp16(sWB + tid * 16, (const char*)g_WtB + tid * 16);
        cp_commit();
    }

    const int lane = tid & 31, wid = tid >> 5;
    const int tile = wid & 1, kt = wid >> 1;
    const int g = lane >> 2, tig = lane & 3;
    const int tb = tile * 16;
    const int kbase = kt * 8 + 2 * tig;

    const float C0  = -0.57735026918962576f;
    const float C1  = -0.70710678118654752f;
    const float C2  =  0.70710678118654752f;
    const float C2z =  0.40824829046386302f;

    float dd[2][4];
    uint2 Ba0, Ba1, Bb0, Bb1;

    // ================= PASS A: streams w0x,w0y,w1y,w1x -> channels 0..4 =====
    {
        unsigned af4[4][2][4];
        #pragma unroll
        for (int kc = 0; kc < 2; ++kc) {
            int jb = kc * 16 + 2 * tig;
            float4 P0 = Bsh[(tb + g) * 32 + jb],         P1 = Bsh[(tb + g) * 32 + jb + 1];
            float4 Q0 = Bsh[(tb + g + 8) * 32 + jb],     Q1 = Bsh[(tb + g + 8) * 32 + jb + 1];
            float4 R0 = Bsh[(tb + g) * 32 + jb + 8],     R1 = Bsh[(tb + g) * 32 + jb + 9];
            float4 S0 = Bsh[(tb + g + 8) * 32 + jb + 8], S1 = Bsh[(tb + g + 8) * 32 + jb + 9];
            af4[0][kc][0]=h2u(P0.x,P1.x); af4[0][kc][1]=h2u(Q0.x,Q1.x); af4[0][kc][2]=h2u(R0.x,R1.x); af4[0][kc][3]=h2u(S0.x,S1.x);
            af4[1][kc][0]=h2u(P0.y,P1.y); af4[1][kc][1]=h2u(Q0.y,Q1.y); af4[1][kc][2]=h2u(R0.y,R1.y); af4[1][kc][3]=h2u(S0.y,S1.y);
            af4[2][kc][0]=h2u(P0.z,P1.z); af4[2][kc][1]=h2u(Q0.z,Q1.z); af4[2][kc][2]=h2u(R0.z,R1.z); af4[2][kc][3]=h2u(S0.z,S1.z);
            af4[3][kc][0]=h2u(P0.w,P1.w); af4[3][kc][1]=h2u(Q0.w,Q1.w); af4[3][kc][2]=h2u(R0.w,R1.w); af4[3][kc][3]=h2u(S0.w,S1.w);
        }
        float acc[5][4];
        #pragma unroll
        for (int c = 0; c < 5; ++c) { acc[c][0]=acc[c][1]=acc[c][2]=acc[c][3]=0.f; }

        for (int i = 0; i < 32; ++i) {
            cp_wait0();
            barall();
            if (i + 1 < 32) {
                const char* src = (const char*)g_WtA + (i + 1) * 8192;
                unsigned dst = sWA + ((i + 1) & 1) * 8192;
                cp16(dst + tid * 16, src + tid * 16);
                cp16(dst + 4096 + tid * 16, src + 4096 + tid * 16);
            }
            cp_commit();

            const uint2* wb = (const uint2*)((const char*)smem + (i & 1) * 8192);
            float4 AL = Ash[(tb + g) * 32 + i];
            float4 AH = Ash[(tb + g + 8) * 32 + i];

            LDB(0, Ba0, Ba1);
            MMA2(af4[0], 0, Ba0, Ba1);                 // m0
            LDB(1, Bb0, Bb1);
            MMA2(af4[1], 1, Bb0, Bb1);                 // m1
            FOLDP(0, 0, AL.x, AH.x);                   // fold m0
            MMA2(af4[2], 0, Bb0, Bb1);                 // m2
            FOLDP(1, 1, AL.y, AH.y);                   // fold m1
            MMA2(af4[3], 1, Bb0, Bb1);                 // m3
            FOLDP(0, 1, AL.z, AH.z);                   // fold m2
            LDB(2, Ba0, Ba1);
            MMA2(af4[0], 0, Ba0, Ba1);                 // m7
            FOLDP(1, 1, AL.w, AH.w);                   // fold m3
            LDB(3, Bb0, Bb1);
            MMA2(af4[1], 1, Bb0, Bb1);                 // m4
            FOLDP(0, 2, AL.y, AH.y);                   // fold m7 (3 channels)
            FOLDP(0, 3, AL.z, AH.z);
            FOLDP(0, 4, AL.w, AH.w);
            MMA2(af4[2], 0, Bb0, Bb1);                 // m5
            FOLDP(1, 2, AL.x, AH.x);                   // fold m4
            MMA2(af4[3], 1, Bb0, Bb1);                 // m6
            FOLDP(0, 3, AL.x, AH.x);                   // fold m5
            FOLDP(1, 4, AL.x, AH.x);                   // fold m6
        }

        // ---- epilogue A: channels 0..4 ----
        #pragma unroll
        for (int eh = 0; eh < 2; ++eh) {
            int node = n0 + tb + (eh ? g + 8 : g);
            if (node >= N) continue;
            float* o = out + (size_t)node * 384;
            #pragma unroll
            for (int ec = 0; ec < 2; ++ec) {
                int e = eh * 2 + ec, c = kbase + ec;
                o[c] = acc[0][e] + C0 * acc[1][e];
                o[32 + 3 * c + 0] = acc[2][e];
                o[32 + 3 * c + 1] = acc[3][e];
                o[32 + 3 * c + 2] = acc[4][e];
            }
        }
    }

    // ================= PASS B: streams w2x,w2y -> channels 5..12 ============
    {
        unsigned af3[3][2][4];
        #pragma unroll
        for (int kc = 0; kc < 2; ++kc) {
            int jb = kc * 16 + 2 * tig;
            float4 P0 = Bsh[(tb + g) * 32 + jb],         P1 = Bsh[(tb + g) * 32 + jb + 1];
            float4 Q0 = Bsh[(tb + g + 8) * 32 + jb],     Q1 = Bsh[(tb + g + 8) * 32 + jb + 1];
            float4 R0 = Bsh[(tb + g) * 32 + jb + 8],     R1 = Bsh[(tb + g) * 32 + jb + 9];
            float4 S0 = Bsh[(tb + g + 8) * 32 + jb + 8], S1 = Bsh[(tb + g + 8) * 32 + jb + 9];
            af3[0][kc][0]=h2u(P0.y,P1.y); af3[0][kc][1]=h2u(Q0.y,Q1.y); af3[0][kc][2]=h2u(R0.y,R1.y); af3[0][kc][3]=h2u(S0.y,S1.y);
            af3[1][kc][0]=h2u(P0.z,P1.z); af3[1][kc][1]=h2u(Q0.z,Q1.z); af3[1][kc][2]=h2u(R0.z,R1.z); af3[1][kc][3]=h2u(S0.z,S1.z);
            af3[2][kc][0]=h2u(P0.w,P1.w); af3[2][kc][1]=h2u(Q0.w,Q1.w); af3[2][kc][2]=h2u(R0.w,R1.w); af3[2][kc][3]=h2u(S0.w,S1.w);
        }
        float acc[8][4];
        #pragma unroll
        for (int c = 0; c < 8; ++c) { acc[c][0]=acc[c][1]=acc[c][2]=acc[c][3]=0.f; }

        for (int i = 0; i < 32; ++i) {
            cp_wait0();
            barall();
            if (i + 1 < 32) {
                const char* src = (const char*)g_WtB + (i + 1) * 4096;
                unsigned dst = sWB + ((i + 1) & 1) * 4096;
                cp16(dst + tid * 16, src + tid * 16);
            }
            cp_commit();

            const uint2* wb = (const uint2*)((const char*)smem + 16384 + (i & 1) * 4096);
            float4 AL = Ash[(tb + g) * 32 + i];
            float4 AH = Ash[(tb + g + 8) * 32 + i];

            LDB(0, Ba0, Ba1);
            MMA2(af3[0], 0, Ba0, Ba1);                 // m8
            MMA2(af3[1], 1, Ba0, Ba1);                 // m9
            FOLDP(0, 1,  AL.w,  AH.w);                 // fold m8
            FOLDP(0, 2, -AL.z, -AH.z);
            MMA2(af3[2], 0, Ba0, Ba1);                 // m10
            FOLDP(1, 2,  AL.y,  AH.y);                 // fold m9
            FOLDP(1, 0, -AL.w, -AH.w);
            LDB(1, Bb0, Bb1);
            MMA2(af3[0], 1, Bb0, Bb1);                 // m11
            FOLDP(0, 0,  AL.z,  AH.z);                 // fold m10
            FOLDP(0, 1, -AL.y, -AH.y);
            MMA2(af3[1], 0, Bb0, Bb1);                 // m12
            FOLDP(1, 3,  AL.w,  AH.w);                 // fold m11
            FOLDP(1, 4,  AL.z,  AH.z);
            FOLDP(1, 5, -AL.y, -AH.y);
            FOLDP(1, 7, -AL.y, -AH.y);
            MMA2(af3[2], 1, Bb0, Bb1);                 // m13
            FOLDP(0, 4,  AL.y,  AH.y);                 // fold m12
            FOLDP(0, 5, 2.f*AL.z, 2.f*AH.z);
            FOLDP(0, 6,  AL.w,  AH.w);
            FOLDP(1, 3,  AL.y,  AH.y);                 // fold m13
            FOLDP(1, 5, -AL.w, -AH.w);
            FOLDP(1, 6,  AL.z,  AH.z);
            FOLDP(1, 7,  AL.w,  AH.w);
        }

        // ---- epilogue B: channels 5..12 ----
        #pragma unroll
        for (int eh = 0; eh < 2; ++eh) {
            int node = n0 + tb + (eh ? g + 8 : g);
            if (node >= N) continue;
            float* o = out + (size_t)node * 384;
            #pragma unroll
            for (int ec = 0; ec < 2; ++ec) {
                int e = eh * 2 + ec, c = kbase + ec;
                o[128 + 3 * c + 0] = C1 * acc[0][e];
                o[128 + 3 * c + 1] = C1 * acc[1][e];
                o[128 + 3 * c + 2] = C1 * acc[2][e];
                o[224 + 5 * c + 0] = C2  * acc[3][e];
                o[224 + 5 * c + 1] = C2  * acc[4][e];
                o[224 + 5 * c + 2] = C2z * acc[5][e];
                o[224 + 5 * c + 3] = C2  * acc[6][e];
                o[224 + 5 * c + 4] = C2  * acc[7][e];
            }
        }
    }
}

extern "C" void kernel_launch(void* const* d_in, const int* in_sizes, int n_in,
                              void* d_out, int out_size)
{
    const float* x     = (const float*)d_in[0];
    const float* W1_0  = (const float*)d_in[1];
    const float* W1_1  = (const float*)d_in[2];
    const float* W2_0  = (const float*)d_in[3];
    const float* W2_1  = (const float*)d_in[4];
    const float* W3_0e = (const float*)d_in[5];
    const float* W3_1o = (const float*)d_in[6];
    const float* W3_1e = (const float*)d_in[7];
    const float* W3_2e = (const float*)d_in[8];

    int N = in_sizes[0] / 128;
    int blocks = (N + NPB - 1) / NPB;
    size_t smem = 65536;

    cudaFuncSetAttribute(td_mma, cudaFuncAttributeMaxDynamicSharedMemorySize,
                         (int)smem);

    pack_w<<<192, 256>>>(W3_0e, W3_1o, W3_1e, W3_2e);
    td_mma<<<blocks, THREADS, smem>>>(x, W1_0, W1_1, W2_0, W2_1,
                                      (float*)d_out, N);
}